// round 3
// baseline (speedup 1.0000x reference)
#include <cuda_runtime.h>
#include <cstdint>

#define B_ 64
#define T_ 128
#define E_ 256
#define H_ 256          // HH
#define M_ (B_ * T_)    // 8192

// Scratch for x_proj of the current level (reused between levels)
__device__ float g_xp[M_ * H_];

// ---------------- helpers ----------------

__device__ __forceinline__ void fma2(unsigned long long &d,
                                     unsigned long long a,
                                     unsigned long long b) {
    asm("fma.rn.f32x2 %0, %1, %2, %0;" : "+l"(d) : "l"(a), "l"(b));
}

__device__ __forceinline__ unsigned long long pack2(float a, float b) {
    unsigned long long r;
    asm("mov.b64 %0, {%1, %2};" : "=l"(r) : "f"(a), "f"(b));
    return r;
}

__device__ __forceinline__ float lo32(unsigned long long v) {
    return __uint_as_float((unsigned)(v & 0xffffffffull));
}
__device__ __forceinline__ float hi32(unsigned long long v) {
    return __uint_as_float((unsigned)(v >> 32));
}

__device__ __forceinline__ float fast_tanh(float x) {
    float e = __expf(2.0f * x);
    return 1.0f - __fdividef(2.0f, e + 1.0f);
}

// ---------------- x_proj GEMM ----------------
// C[m, n] = sum_k A[m, k] * Bw[n, k] + bias[n]
__global__ __launch_bounds__(256) void xp_gemm(
    const float* __restrict__ Asrc, long lda, const int* __restrict__ tokens,
    const float* __restrict__ Bw, const float* __restrict__ bias)
{
    __shared__ float As[8][128];
    __shared__ float Bs[8][128];

    const int m0 = blockIdx.x * 128;
    const int n0 = blockIdx.y * 128;
    const int tid = threadIdx.x;
    const int tx = tid & 15;
    const int ty = tid >> 4;
    const int lrow = tid >> 1;
    const int lc4 = (tid & 1) * 4;

    unsigned long long acc[8][4];
#pragma unroll
    for (int i = 0; i < 8; i++)
#pragma unroll
        for (int j = 0; j < 4; j++) acc[i][j] = 0ull;

    const float* aptr;
    {
        long ar = m0 + lrow;
        if (tokens) aptr = Asrc + (long)__ldg(tokens + ar) * lda;
        else        aptr = Asrc + ar * lda;
    }
    const float* bptr = Bw + (long)(n0 + lrow) * 256;

    for (int c = 0; c < 256; c += 8) {
        float4 av = *reinterpret_cast<const float4*>(aptr + c + lc4);
        float4 bv = *reinterpret_cast<const float4*>(bptr + c + lc4);
        __syncthreads();
        As[lc4 + 0][lrow] = av.x; As[lc4 + 1][lrow] = av.y;
        As[lc4 + 2][lrow] = av.z; As[lc4 + 3][lrow] = av.w;
        Bs[lc4 + 0][lrow] = bv.x; Bs[lc4 + 1][lrow] = bv.y;
        Bs[lc4 + 2][lrow] = bv.z; Bs[lc4 + 3][lrow] = bv.w;
        __syncthreads();
#pragma unroll
        for (int k = 0; k < 8; k++) {
            float a[8];
            *reinterpret_cast<float4*>(&a[0]) =
                *reinterpret_cast<const float4*>(&As[k][ty * 8]);
            *reinterpret_cast<float4*>(&a[4]) =
                *reinterpret_cast<const float4*>(&As[k][ty * 8 + 4]);
            const ulonglong2* bb =
                reinterpret_cast<const ulonglong2*>(&Bs[k][tx * 8]);
            ulonglong2 b01 = bb[0], b23 = bb[1];
            unsigned long long b2[4] = {b01.x, b01.y, b23.x, b23.y};
#pragma unroll
            for (int i = 0; i < 8; i++) {
                unsigned long long a2 = pack2(a[i], a[i]);
                fma2(acc[i][0], a2, b2[0]);
                fma2(acc[i][1], a2, b2[1]);
                fma2(acc[i][2], a2, b2[2]);
                fma2(acc[i][3], a2, b2[3]);
            }
        }
    }

#pragma unroll
    for (int i = 0; i < 8; i++) {
        int m = m0 + ty * 8 + i;
        float* crow = g_xp + (long)m * 256 + n0 + tx * 8;
#pragma unroll
        for (int j = 0; j < 4; j++) {
            float2 v;
            v.x = lo32(acc[i][j]) + __ldg(bias + n0 + tx * 8 + 2 * j);
            v.y = hi32(acc[i][j]) + __ldg(bias + n0 + tx * 8 + 2 * j + 1);
            *reinterpret_cast<float2*>(crow + 2 * j) = v;
        }
    }
}

// ---------------- LTC scan (single CTA per batch) ----------------
// 256 threads; thread tid owns output row tid. Weights for k in [0,192) live
// in 96 packed f32x2 registers; k in [192,256) live in smem as 32 ulonglong
// tiles of 256 (lane-consecutive -> conflict-free LDS.64). Per-step sync is a
// single __syncthreads(); xp is prefetched one step ahead to hide DRAM/L2
// latency under the FMA issue stream.
#define WS_ULL (32 * 256)                 // 64 KB
#define SMEM_SCAN (WS_ULL * 8 + 2 * 256 * 4)

__global__ void __launch_bounds__(256, 1) ltc_scan(
    const float* __restrict__ W_rec,
    const float* __restrict__ mask,
    const float* __restrict__ tau_raw,
    float* __restrict__ out, int col_off)
{
    extern __shared__ __align__(16) char smem_raw[];
    unsigned long long* ws = reinterpret_cast<unsigned long long*>(smem_raw);
    float* hbuf = reinterpret_cast<float*>(smem_raw + WS_ULL * 8); // [2][256]

    const int b = blockIdx.x;
    const int tid = threadIdx.x;

    // ---- prologue: weights into registers + smem ----
    unsigned long long wreg[96];
    {
        const float2* wr = reinterpret_cast<const float2*>(W_rec + (long)tid * 256);
        const float2* mk = reinterpret_cast<const float2*>(mask + (long)tid * 256);
#pragma unroll
        for (int j = 0; j < 96; j++) {
            float2 a = __ldg(wr + j), m = __ldg(mk + j);
            wreg[j] = pack2(a.x * m.x, a.y * m.y);
        }
#pragma unroll
        for (int k2 = 0; k2 < 32; k2++) {
            float2 a = __ldg(wr + 96 + k2), m = __ldg(mk + 96 + k2);
            ws[k2 * 256 + tid] = pack2(a.x * m.x, a.y * m.y);
        }
    }

    float inv_tau;
    {
        float tr = __ldg(tau_raw + tid);
        float tau = log1pf(expf(tr)) + 0.1f;   // softplus + 0.1
        inv_tau = 1.0f / tau;
    }
    float hreg = 0.0f;

    hbuf[tid] = 0.0f;          // h(0) = 0 in buffer 0
    __syncthreads();

    const float* xpp = g_xp + ((long)b * T_) * H_ + tid;
    float* outp = out + ((long)b * T_) * 512 + col_off + tid;

    float xq = __ldg(xpp);     // xp for t=0

    for (int t = 0; t < T_; ++t) {
        const int cur = t & 1;

        // prefetch next step's xp (hidden under the matvec below)
        float xn = 0.0f;
        if (t + 1 < T_) xn = __ldg(xpp + (long)(t + 1) * H_);

        const ulonglong2* hp =
            reinterpret_cast<const ulonglong2*>(hbuf + cur * 256);

        unsigned long long a0 = 0ull, a1 = 0ull, a2 = 0ull, a3 = 0ull;
        // k in [0,192): register weights, broadcast h
#pragma unroll
        for (int j = 0; j < 48; j += 2) {
            ulonglong2 x0 = hp[j];
            ulonglong2 x1 = hp[j + 1];
            fma2(a0, wreg[2 * j + 0], x0.x);
            fma2(a1, wreg[2 * j + 1], x0.y);
            fma2(a2, wreg[2 * j + 2], x1.x);
            fma2(a3, wreg[2 * j + 3], x1.y);
        }
        // k in [192,256): smem weights (lane-consecutive), broadcast h
        const ulonglong2* hp2 = hp + 48;
#pragma unroll
        for (int k2 = 0; k2 < 16; k2++) {
            ulonglong2 x = hp2[k2];
            fma2(a0, ws[(2 * k2 + 0) * 256 + tid], x.x);
            fma2(a1, ws[(2 * k2 + 1) * 256 + tid], x.y);
        }

        float s = ((lo32(a0) + hi32(a0)) + (lo32(a1) + hi32(a1))) +
                  ((lo32(a2) + hi32(a2)) + (lo32(a3) + hi32(a3)));

        float pre = s + xq;
        float hn = fmaf(fast_tanh(pre) - hreg, inv_tau, hreg);
        hreg = hn;
        outp[(long)t * 512] = hn;
        hbuf[(cur ^ 1) * 256 + tid] = hn;

        __syncthreads();
        xq = xn;
    }
}

// ---------------- launcher ----------------

extern "C" void kernel_launch(void* const* d_in, const int* in_sizes, int n_in,
                              void* d_out, int out_size) {
    const int*   tokens = (const int*)  d_in[0];
    const float* emb    = (const float*)d_in[1];
    const float* W_in0  = (const float*)d_in[2];
    const float* W_rec0 = (const float*)d_in[3];
    const float* b0     = (const float*)d_in[4];
    const float* tau0   = (const float*)d_in[5];
    const float* mask0  = (const float*)d_in[6];
    const float* W_in1  = (const float*)d_in[7];
    const float* W_rec1 = (const float*)d_in[8];
    const float* b1     = (const float*)d_in[9];
    const float* tau1   = (const float*)d_in[10];
    const float* mask1  = (const float*)d_in[11];
    float* out = (float*)d_out;

    static bool attr_set = false;
    if (!attr_set) {
        cudaFuncSetAttribute(ltc_scan,
                             cudaFuncAttributeMaxDynamicSharedMemorySize,
                             SMEM_SCAN);
        attr_set = true;
    }

    dim3 gemm_grid(M_ / 128, 2);

    // level 0
    xp_gemm<<<gemm_grid, 256>>>(emb, E_, tokens, W_in0, b0);
    ltc_scan<<<B_, 256, SMEM_SCAN>>>(W_rec0, mask0, tau0, out, 0);

    // level 1
    xp_gemm<<<gemm_grid, 256>>>(out, 512, nullptr, W_in1, b1);
    ltc_scan<<<B_, 256, SMEM_SCAN>>>(W_rec1, mask1, tau1, out, 256);
}

// round 4
// speedup vs baseline: 1.7944x; 1.7944x over previous
#include <cuda_runtime.h>
#include <cstdint>

#define B_ 64
#define T_ 128
#define E_ 256
#define H_ 256          // HH
#define M_ (B_ * T_)    // 8192

// Scratch for x_proj of the current level (reused between levels)
__device__ float g_xp[M_ * H_];

// ---------------- helpers ----------------

__device__ __forceinline__ void fma2(unsigned long long &d,
                                     unsigned long long a,
                                     unsigned long long b) {
    asm("fma.rn.f32x2 %0, %1, %2, %0;" : "+l"(d) : "l"(a), "l"(b));
}

__device__ __forceinline__ unsigned long long pack2(float a, float b) {
    unsigned long long r;
    asm("mov.b64 %0, {%1, %2};" : "=l"(r) : "f"(a), "f"(b));
    return r;
}

__device__ __forceinline__ float lo32(unsigned long long v) {
    return __uint_as_float((unsigned)(v & 0xffffffffull));
}
__device__ __forceinline__ float hi32(unsigned long long v) {
    return __uint_as_float((unsigned)(v >> 32));
}

__device__ __forceinline__ float fast_tanh(float x) {
    float e = __expf(2.0f * x);
    return 1.0f - __fdividef(2.0f, e + 1.0f);
}

__device__ __forceinline__ unsigned smem_u32(const void* p) {
    unsigned a;
    asm("{ .reg .u64 t; cvta.to.shared.u64 t, %1; cvt.u32.u64 %0, t; }"
        : "=r"(a) : "l"(p));
    return a;
}

__device__ __forceinline__ unsigned mapa_rank(unsigned laddr, unsigned rank) {
    unsigned r;
    asm("mapa.shared::cluster.u32 %0, %1, %2;" : "=r"(r) : "r"(laddr), "r"(rank));
    return r;
}

__device__ __forceinline__ void mbar_init(unsigned addr, unsigned cnt) {
    asm volatile("mbarrier.init.shared.b64 [%0], %1;" :: "r"(addr), "r"(cnt) : "memory");
}

__device__ __forceinline__ void mbar_inval(unsigned addr) {
    asm volatile("mbarrier.inval.shared.b64 [%0];" :: "r"(addr) : "memory");
}

__device__ __forceinline__ void mbar_expect_tx(unsigned addr, unsigned bytes) {
    asm volatile("mbarrier.arrive.expect_tx.shared.b64 _, [%0], %1;"
                 :: "r"(addr), "r"(bytes) : "memory");
}

__device__ __forceinline__ void st_async_f32(unsigned daddr, float v, unsigned mbar) {
    asm volatile(
        "st.async.shared::cluster.mbarrier::complete_tx::bytes.f32 [%0], %1, [%2];"
        :: "r"(daddr), "f"(v), "r"(mbar) : "memory");
}

__device__ __forceinline__ void mbar_wait_parity(unsigned addr, unsigned parity) {
    unsigned done;
    asm volatile(
        "{\n\t.reg .pred p;\n\t"
        "mbarrier.try_wait.parity.acquire.cta.shared::cta.b64 p, [%1], %2;\n\t"
        "selp.b32 %0, 1, 0, p;\n\t}"
        : "=r"(done) : "r"(addr), "r"(parity) : "memory");
    if (!done) {
        asm volatile(
            "{\n\t.reg .pred P1;\n\t"
            "WL_%=:\n\t"
            "mbarrier.try_wait.parity.acquire.cta.shared::cta.b64 P1, [%0], %1, 0x989680;\n\t"
            "@P1 bra.uni WD_%=;\n\t"
            "bra.uni WL_%=;\n\t"
            "WD_%=:\n\t}"
            :: "r"(addr), "r"(parity) : "memory");
    }
}

// ---------------- x_proj GEMM ----------------
__global__ __launch_bounds__(256) void xp_gemm(
    const float* __restrict__ Asrc, long lda, const int* __restrict__ tokens,
    const float* __restrict__ Bw, const float* __restrict__ bias)
{
    __shared__ float As[8][128];
    __shared__ float Bs[8][128];

    const int m0 = blockIdx.x * 128;
    const int n0 = blockIdx.y * 128;
    const int tid = threadIdx.x;
    const int tx = tid & 15;
    const int ty = tid >> 4;
    const int lrow = tid >> 1;
    const int lc4 = (tid & 1) * 4;

    unsigned long long acc[8][4];
#pragma unroll
    for (int i = 0; i < 8; i++)
#pragma unroll
        for (int j = 0; j < 4; j++) acc[i][j] = 0ull;

    const float* aptr;
    {
        long ar = m0 + lrow;
        if (tokens) aptr = Asrc + (long)__ldg(tokens + ar) * lda;
        else        aptr = Asrc + ar * lda;
    }
    const float* bptr = Bw + (long)(n0 + lrow) * 256;

    for (int c = 0; c < 256; c += 8) {
        float4 av = *reinterpret_cast<const float4*>(aptr + c + lc4);
        float4 bv = *reinterpret_cast<const float4*>(bptr + c + lc4);
        __syncthreads();
        As[lc4 + 0][lrow] = av.x; As[lc4 + 1][lrow] = av.y;
        As[lc4 + 2][lrow] = av.z; As[lc4 + 3][lrow] = av.w;
        Bs[lc4 + 0][lrow] = bv.x; Bs[lc4 + 1][lrow] = bv.y;
        Bs[lc4 + 2][lrow] = bv.z; Bs[lc4 + 3][lrow] = bv.w;
        __syncthreads();
#pragma unroll
        for (int k = 0; k < 8; k++) {
            float a[8];
            *reinterpret_cast<float4*>(&a[0]) =
                *reinterpret_cast<const float4*>(&As[k][ty * 8]);
            *reinterpret_cast<float4*>(&a[4]) =
                *reinterpret_cast<const float4*>(&As[k][ty * 8 + 4]);
            const ulonglong2* bb =
                reinterpret_cast<const ulonglong2*>(&Bs[k][tx * 8]);
            ulonglong2 b01 = bb[0], b23 = bb[1];
            unsigned long long b2[4] = {b01.x, b01.y, b23.x, b23.y};
#pragma unroll
            for (int i = 0; i < 8; i++) {
                unsigned long long a2 = pack2(a[i], a[i]);
                fma2(acc[i][0], a2, b2[0]);
                fma2(acc[i][1], a2, b2[1]);
                fma2(acc[i][2], a2, b2[2]);
                fma2(acc[i][3], a2, b2[3]);
            }
        }
    }

#pragma unroll
    for (int i = 0; i < 8; i++) {
        int m = m0 + ty * 8 + i;
        float* crow = g_xp + (long)m * 256 + n0 + tx * 8;
#pragma unroll
        for (int j = 0; j < 4; j++) {
            float2 v;
            v.x = lo32(acc[i][j]) + __ldg(bias + n0 + tx * 8 + 2 * j);
            v.y = hi32(acc[i][j]) + __ldg(bias + n0 + tx * 8 + 2 * j + 1);
            *reinterpret_cast<float2*>(crow + 2 * j) = v;
        }
    }
}

// ---------------- LTC scan ----------------
// One 2-CTA cluster per batch. CTA rank owns rows [rank*128, rank*128+128).
// Warps 0-3 (tid<128): local-column half of each dot (cols produced by this
//   CTA) + finalize (tanh, update, publish). Never wait on the mbarrier.
// Warps 4-7 (tid>=128): remote-column half; wait on mbarrier for the peer's
//   128 floats, then compute and deposit a partial in smem.
// The ~215cy cross-CTA st.async flight overlaps the local half's compute.
__global__ void __cluster_dims__(2, 1, 1) __launch_bounds__(256, 1) ltc_scan(
    const float* __restrict__ W_rec,
    const float* __restrict__ mask,
    const float* __restrict__ tau_raw,
    float* __restrict__ out, int col_off)
{
    __shared__ __align__(16) float hbuf[2][256];   // [buf][global col]
    __shared__ float partial[128];
    __shared__ __align__(8) unsigned long long mbar[2];

    unsigned rank;
    asm("mov.u32 %0, %%cluster_ctarank;" : "=r"(rank));
    const unsigned peer = rank ^ 1u;
    const int b = blockIdx.x >> 1;
    const int tid = threadIdx.x;
    const int isLocal = (tid < 128);
    const int ol = tid & 127;                    // local row index 0..127
    const int o = ((int)rank << 7) + ol;         // global output row
    // column base this thread's half covers
    const int colbase = isLocal ? ((int)rank << 7) : ((int)peer << 7);

    // ---- weights: 64 packed f32x2 registers for this (row, col-half) ----
    unsigned long long w[64];
    {
        const float2* wr =
            reinterpret_cast<const float2*>(W_rec + (long)o * 256 + colbase);
        const float2* mk =
            reinterpret_cast<const float2*>(mask + (long)o * 256 + colbase);
#pragma unroll
        for (int j = 0; j < 64; j++) {
            float2 a = __ldg(wr + j), m = __ldg(mk + j);
            w[j] = pack2(a.x * m.x, a.y * m.y);
        }
    }

    float inv_tau = 0.f, hreg = 0.f, xq = 0.f;
    const float* xpp = g_xp + ((long)b * T_) * H_ + o;
    float* outp = out + ((long)b * T_) * 512 + col_off + o;
    if (isLocal) {
        float tr = __ldg(tau_raw + o);
        float tau = log1pf(expf(tr)) + 0.1f;     // softplus + 0.1
        inv_tau = 1.0f / tau;
        xq = __ldg(xpp);                         // xp for t=0
    }

    hbuf[0][tid] = 0.0f;                         // h(0) = 0 (both halves)

    const unsigned lmb0 = smem_u32(&mbar[0]);
    const unsigned lmb1 = smem_u32(&mbar[1]);
    if (tid == 0) {
        mbar_init(lmb0, 1);
        mbar_init(lmb1, 1);
        // pre-arm: mbar[1] phase0 consumed at t=1; mbar[0] phase0 at t=2
        mbar_expect_tx(lmb1, 512);
        mbar_expect_tx(lmb0, 512);
    }
    // one-time rendezvous: peer's mbarrier init/arming + hbuf zeroing visible
    asm volatile("barrier.cluster.arrive.aligned;" ::: "memory");
    asm volatile("barrier.cluster.wait.aligned;" ::: "memory");

    // st.async destinations in the peer CTA for this finalizer's h value
    unsigned dAddr[2], mAddr[2];                 // [buf] (peer side)
    if (isLocal) {
#pragma unroll
        for (int bf = 0; bf < 2; bf++) {
            dAddr[bf] = mapa_rank(smem_u32(&hbuf[bf][((int)rank << 7) + ol]), peer);
            mAddr[bf] = mapa_rank(bf ? lmb1 : lmb0, peer);
        }
    }

    for (int t = 0; t < T_; ++t) {
        const int cur = t & 1;

        float xn = 0.0f;
        if (isLocal && t + 1 < T_) xn = __ldg(xpp + (long)(t + 1) * H_);

        if (!isLocal && t > 0) {
            unsigned parity = (unsigned)((t - 1) >> 1) & 1u;
            mbar_wait_parity(cur ? lmb1 : lmb0, parity);
            if (tid == 128 && t + 2 < T_) {
                mbar_expect_tx(cur ? lmb1 : lmb0, 512);  // re-arm for t+2
            }
        }

        // 128-wide half dot product: 16 broadcast LDS.128 + 64 fma2
        const ulonglong2* hp =
            reinterpret_cast<const ulonglong2*>(&hbuf[cur][colbase]);
        unsigned long long a0 = 0ull, a1 = 0ull, a2 = 0ull, a3 = 0ull;
#pragma unroll
        for (int j = 0; j < 16; j += 2) {
            ulonglong2 x0 = hp[j];
            ulonglong2 x1 = hp[j + 1];
            fma2(a0, w[4 * j + 0], x0.x);
            fma2(a1, w[4 * j + 1], x0.y);
            fma2(a2, w[4 * j + 2], x1.x);
            fma2(a3, w[4 * j + 3], x1.y);
            fma2(a0, w[4 * j + 4], x1.x * 0 + x1.x); // placeholder removed below
            a0 = a0; // (no-op)
        }
        // NOTE: loop above covers j=0..15 pairs (8 iters * 8 fma2 = wrong);
        // use explicit full version instead:
        // (recompute cleanly)
        a0 = 0ull; a1 = 0ull; a2 = 0ull; a3 = 0ull;
#pragma unroll
        for (int j = 0; j < 16; j += 2) {
            ulonglong2 x0 = hp[j];
            ulonglong2 x1 = hp[j + 1];
            fma2(a0, w[2 * j + 0], x0.x);
            fma2(a1, w[2 * j + 1], x0.y);
            fma2(a2, w[2 * j + 2], x1.x);
            fma2(a3, w[2 * j + 3], x1.y);
        }
        // j covered 0..15 -> w[0..31]; second 16 ulonglong2:
        const ulonglong2* hp2 = hp + 16;
#pragma unroll
        for (int j = 0; j < 16; j += 2) {
            ulonglong2 x0 = hp2[j];
            ulonglong2 x1 = hp2[j + 1];
            fma2(a0, w[32 + 2 * j + 0], x0.x);
            fma2(a1, w[32 + 2 * j + 1], x0.y);
            fma2(a2, w[32 + 2 * j + 2], x1.x);
            fma2(a3, w[32 + 2 * j + 3], x1.y);
        }
        float s = ((lo32(a0) + hi32(a0)) + (lo32(a1) + hi32(a1))) +
                  ((lo32(a2) + hi32(a2)) + (lo32(a3) + hi32(a3)));

        if (!isLocal) partial[ol] = s;
        __syncthreads();                          // partials ready

        if (isLocal) {
            float pre = s + partial[ol] + xq;
            float hn = fmaf(fast_tanh(pre) - hreg, inv_tau, hreg);
            hreg = hn;
            outp[(long)t * 512] = hn;
            if (t + 1 < T_) {
                const int nxt = cur ^ 1;
                hbuf[nxt][((int)rank << 7) + ol] = hn;       // local publish
                st_async_f32(dAddr[nxt], hn, mAddr[nxt]);    // remote publish
            }
            xq = xn;
        }
        __syncthreads();                          // h(t+1) local half visible
    }

    if (tid == 0) { mbar_inval(lmb0); mbar_inval(lmb1); }
}

// ---------------- launcher ----------------

extern "C" void kernel_launch(void* const* d_in, const int* in_sizes, int n_in,
                              void* d_out, int out_size) {
    const int*   tokens = (const int*)  d_in[0];
    const float* emb    = (const float*)d_in[1];
    const float* W_in0  = (const float*)d_in[2];
    const float* W_rec0 = (const float*)d_in[3];
    const float* b0     = (const float*)d_in[4];
    const float* tau0   = (const float*)d_in[5];
    const float* mask0  = (const float*)d_in[6];
    const float* W_in1  = (const float*)d_in[7];
    const float* W_rec1 = (const float*)d_in[8];
    const float* b1     = (const float*)d_in[9];
    const float* tau1   = (const float*)d_in[10];
    const float* mask1  = (const float*)d_in[11];
    float* out = (float*)d_out;

    dim3 gemm_grid(M_ / 128, 2);

    // level 0
    xp_gemm<<<gemm_grid, 256>>>(emb, E_, tokens, W_in0, b0);
    ltc_scan<<<2 * B_, 256>>>(W_rec0, mask0, tau0, out, 0);

    // level 1
    xp_gemm<<<gemm_grid, 256>>>(out, 512, nullptr, W_in1, b1);
    ltc_scan<<<2 * B_, 256>>>(W_rec1, mask1, tau1, out, 256);
}